// round 16
// baseline (speedup 1.0000x reference)
#include <cuda_runtime.h>
#include <cstdint>

// Filtering_72773925863700
// out[b,m,n,i] = (F x)_along_m + (F x)_along_n,  F = C C^T (256x32 low-rank).
// B=8, M=N=256, I=32, fp32.
//
// Round 16: k1/k2 per-thread work halved (4k x 4j / 4k x 4i) with 256-thread
// blocks -> 2x resident warps (occ 20.7% -> ~42%) to lift the measured
// fma-issue ceiling (47.9%). k3a/k3b (tensor, A-frag precompute) and inits
// unchanged from the 114.7us R15 kernel.

#define BATCH 8
#define MDIM 256
#define NDIM 256
#define IDIM 32
#define KM 32
#define NI (NDIM * IDIM)   // 8192

__device__ float d_C[MDIM * KM];           // C[n][k] fp32 (k1/k2 staging)
__device__ float d_Ct[MDIM * KM];          // C[n][k] tf32-rounded
__device__ float d_Afrag[16 * 4 * 32 * 4]; // [rf][kf][lane][4] mma A frags
__device__ float d_D1[BATCH * KM * NI];    // [b][k][(n,i)]  tf32 values
__device__ float d_D2[BATCH * KM * NI];    // [b][k][(m,i)]  tf32 values

union F4U { float4 f4; uint64_t u[2]; float f[4]; };
union U4F { uint4 u4; uint32_t u[4]; };

__device__ __forceinline__ uint64_t pack2(float c) {
    uint64_t r;
    asm("mov.b64 %0, {%1, %1};" : "=l"(r) : "f"(c));
    return r;
}
__device__ __forceinline__ void fma2(uint64_t& acc, uint64_t a, uint64_t b) {
    asm("fma.rn.f32x2 %0, %1, %2, %0;" : "+l"(acc) : "l"(a), "l"(b));
}
__device__ __forceinline__ uint32_t tf32_bits(float x) {
    uint32_t r;
    asm("cvt.rna.tf32.f32 %0, %1;" : "=r"(r) : "f"(x));
    return r;
}
__device__ __forceinline__ uint32_t sm_addr(const void* p) {
    uint32_t a;
    asm("{ .reg .u64 t; cvta.to.shared.u64 t, %1; cvt.u32.u64 %0, t; }"
        : "=r"(a) : "l"(p));
    return a;
}
__device__ __forceinline__ void mbar_init(uint32_t mbar, uint32_t count) {
    asm volatile("mbarrier.init.shared.b64 [%0], %1;" :: "r"(mbar), "r"(count) : "memory");
}
__device__ __forceinline__ void mbar_expect(uint32_t mbar, uint32_t bytes) {
    asm volatile("mbarrier.arrive.expect_tx.shared.b64 _, [%0], %1;"
                 :: "r"(mbar), "r"(bytes) : "memory");
}
__device__ __forceinline__ void bulk_g2s(uint32_t dst, const void* src,
                                         uint32_t bytes, uint32_t mbar) {
    asm volatile(
        "cp.async.bulk.shared::cta.global.mbarrier::complete_tx::bytes [%0], [%1], %2, [%3];"
        :: "r"(dst), "l"(src), "r"(bytes), "r"(mbar) : "memory");
}
__device__ __forceinline__ void mbar_wait(uint32_t mbar, uint32_t parity) {
    asm volatile(
        "{\n\t"
        ".reg .pred P1;\n\t"
        "WAIT_LOOP_%=:\n\t"
        "mbarrier.try_wait.parity.acquire.cta.shared::cta.b64 P1, [%0], %1;\n\t"
        "@P1 bra.uni WAIT_DONE_%=;\n\t"
        "bra.uni WAIT_LOOP_%=;\n\t"
        "WAIT_DONE_%=:\n\t"
        "}"
        :: "r"(mbar), "r"(parity) : "memory");
}
// mma.sync m16n8k8 tf32: D += A x B (mapping verified R11/R13/R14/R15).
__device__ __forceinline__ void mma_tf32(float* d, const uint32_t* a,
                                         uint32_t b0, uint32_t b1) {
    asm volatile(
        "mma.sync.aligned.m16n8k8.row.col.f32.tf32.tf32.f32 "
        "{%0,%1,%2,%3}, {%4,%5,%6,%7}, {%8,%9}, {%0,%1,%2,%3};"
        : "+f"(d[0]), "+f"(d[1]), "+f"(d[2]), "+f"(d[3])
        : "r"(a[0]), "r"(a[1]), "r"(a[2]), "r"(a[3]), "r"(b0), "r"(b1));
}
__device__ __forceinline__ void st_tf32x4(float* p, const float* v) {
    F4U o;
    o.f[0] = __uint_as_float(tf32_bits(v[0]));
    o.f[1] = __uint_as_float(tf32_bits(v[1]));
    o.f[2] = __uint_as_float(tf32_bits(v[2]));
    o.f[3] = __uint_as_float(tf32_bits(v[3]));
    *(float4*)p = o.f4;
}

// ---------------------------------------------------------------------------
// Init C (fp32 + tf32).
// ---------------------------------------------------------------------------
__global__ void init_C_kernel() {
    int idx = blockIdx.x * 256 + threadIdx.x;   // 8192
    int n = idx >> 5;
    int j = idx & 31;
    const double PI = 3.14159265358979323846;
    const double AMP = 1.4142135623730951 / 16.0;
    double v;
    if (j == 0) {
        v = 1.0 / 16.0;
    } else if (j <= 15) {
        int ph = (j * n) & 255;
        v = AMP * cos(2.0 * PI * (double)ph / 256.0);
    } else if (j <= 30) {
        int k = j - 15;
        int ph = (k * n) & 255;
        v = AMP * sin(2.0 * PI * (double)ph / 256.0);
    } else {
        v = 0.0;
    }
    float f = (float)v;
    d_C[idx]  = f;
    d_Ct[idx] = __uint_as_float(tf32_bits(f));
}

// Pack Ct into mma A-fragment order: [rf][kf][lane] -> float4 (a0,a1,a2,a3).
__global__ void init_A_kernel() {
    int idx = blockIdx.x * 256 + threadIdx.x;   // 2048 = 16*4*32
    int lane = idx & 31;
    int kf = (idx >> 5) & 3;
    int rf = idx >> 7;
    int gr = lane >> 2, tg = lane & 3;
    int r0 = rf * 16, c = kf * 8 + tg;
    float4 v;
    v.x = d_Ct[(r0 + gr) * 32 + c];
    v.y = d_Ct[(r0 + 8 + gr) * 32 + c];
    v.z = d_Ct[(r0 + gr) * 32 + c + 4];
    v.w = d_Ct[(r0 + 8 + gr) * 32 + c + 4];
    ((float4*)d_Afrag)[idx] = v;
}

// ---------------------------------------------------------------------------
// K1: D1[b,k,(n,i)] = sum_m C[m,k] x[b,m,(n,i)].  Scalar fp32, bulk-async.
// Grid (64, 8), 256 thr. Tile [32k x 128j]; 16 chunks of 16 m.
// Thread: ko=t>>5 (4 k's: ko*4..+3), jq=t&31 (one float4 of j).
// ---------------------------------------------------------------------------
__global__ void __launch_bounds__(256) k1_down_m(const float* __restrict__ x) {
    __shared__ __align__(128) float xs[2][16 * 128];   // 8 KB each
    __shared__ __align__(128) float cs[2][16 * 32];    // 2 KB each
    __shared__ __align__(8) uint64_t mbar[2];

    int t  = threadIdx.x;
    int b  = blockIdx.y;
    int j0 = blockIdx.x * 128;
    int jq = t & 31;
    int ko = t >> 5;   // 0..7 -> 4 k's each

    const float* xb = x + (size_t)b * (MDIM * NI);
    uint32_t mb0 = sm_addr(&mbar[0]);
    uint32_t mb1 = sm_addr(&mbar[1]);

    if (t == 0) { mbar_init(mb0, 1); mbar_init(mb1, 1); }
    __syncthreads();

    const uint32_t CHUNK_BYTES = 16 * 128 * 4 + 16 * 32 * 4;   // 10240

    auto issue = [&](int mc, int s) {
        uint32_t mb = s ? mb1 : mb0;
        mbar_expect(mb, CHUNK_BYTES);
#pragma unroll
        for (int mm = 0; mm < 16; mm++)
            bulk_g2s(sm_addr(&xs[s][mm * 128]),
                     &xb[(size_t)(mc * 16 + mm) * NI + j0], 512, mb);
        bulk_g2s(sm_addr(&cs[s][0]), &d_C[mc * 16 * 32], 2048, mb);
    };

    uint64_t acc[4][2];
#pragma unroll
    for (int a = 0; a < 4; a++) { acc[a][0] = 0ull; acc[a][1] = 0ull; }

    if (t == 0) issue(0, 0);
    for (int mc = 0; mc < 16; mc++) {
        int s = mc & 1;
        if (mc + 1 < 16) {
            __syncthreads();
            if (t == 0) issue(mc + 1, s ^ 1);
        }
        mbar_wait(s ? mb1 : mb0, (mc >> 1) & 1);

        const float* xsb = xs[s];
        const float* csb = cs[s];
#pragma unroll
        for (int mm = 0; mm < 16; mm++) {
            F4U xv; xv.f4 = *(const float4*)&xsb[mm * 128 + jq * 4];
            F4U cv; cv.f4 = *(const float4*)&csb[mm * 32 + ko * 4];
#pragma unroll
            for (int a = 0; a < 4; a++) {
                uint64_t cp = pack2(cv.f[a]);
                fma2(acc[a][0], cp, xv.u[0]);
                fma2(acc[a][1], cp, xv.u[1]);
            }
        }
    }

#pragma unroll
    for (int a = 0; a < 4; a++) {
        int k = ko * 4 + a;
        F4U v; v.u[0] = acc[a][0]; v.u[1] = acc[a][1];
        st_tf32x4(&d_D1[((size_t)b * 32 + k) * NI + j0 + jq * 4], v.f);
    }
}

// ---------------------------------------------------------------------------
// K2: D2[b,k,(m,i)] = sum_n C[n,k] x[b,m,n,i].  Scalar fp32, bulk-async.
// Grid (64, 8), 256 thr. Tile 4 m; 16 chunks of 16 n.
// Thread: kq=t&7 (4 k's: kq*4..+3), iq=(t>>3)&7 (4 i), ml=t>>6 (warp-unif m).
// ---------------------------------------------------------------------------
__global__ void __launch_bounds__(256) k2_down_n(const float* __restrict__ x) {
    __shared__ __align__(128) float zs[2][4 * 16 * 32];   // 8 KB each
    __shared__ __align__(128) float ch[2][16 * 32];       // 2 KB each
    __shared__ __align__(8) uint64_t mbar[2];

    int t  = threadIdx.x;
    int b  = blockIdx.y;
    int m0 = blockIdx.x * 4;
    int kq = t & 7;          // 4 k's each
    int iq = (t >> 3) & 7;   // 4 i
    int ml = t >> 6;         // 0..3, warp-uniform

    const float* xb = x + (size_t)b * (MDIM * NI) + (size_t)m0 * NI;
    uint32_t mb0 = sm_addr(&mbar[0]);
    uint32_t mb1 = sm_addr(&mbar[1]);

    if (t == 0) { mbar_init(mb0, 1); mbar_init(mb1, 1); }
    __syncthreads();

    const uint32_t CHUNK_BYTES = 4 * 16 * 32 * 4 + 16 * 32 * 4;   // 10240

    auto issue = [&](int nc, int s) {
        uint32_t mb = s ? mb1 : mb0;
        mbar_expect(mb, CHUNK_BYTES);
#pragma unroll
        for (int m2 = 0; m2 < 4; m2++)
            bulk_g2s(sm_addr(&zs[s][m2 * 16 * 32]),
                     &xb[(size_t)m2 * NI + nc * 16 * 32], 2048, mb);
        bulk_g2s(sm_addr(&ch[s][0]), &d_C[nc * 16 * 32], 2048, mb);
    };

    uint64_t acc[4][2];
#pragma unroll
    for (int kk = 0; kk < 4; kk++) { acc[kk][0] = 0ull; acc[kk][1] = 0ull; }

    if (t == 0) issue(0, 0);
    for (int nc = 0; nc < 16; nc++) {
        int s = nc & 1;
        if (nc + 1 < 16) {
            __syncthreads();
            if (t == 0) issue(nc + 1, s ^ 1);
        }
        mbar_wait(s ? mb1 : mb0, (nc >> 1) & 1);

        const float* zb = zs[s];
        const float* cb = ch[s];
#pragma unroll
        for (int nn = 0; nn < 16; nn++) {
            F4U z; z.f4 = *(const float4*)&zb[(ml * 16 + nn) * 32 + iq * 4];
            F4U c; c.f4 = *(const float4*)&cb[nn * 32 + kq * 4];
#pragma unroll
            for (int kk = 0; kk < 4; kk++) {
                uint64_t cp = pack2(c.f[kk]);
                fma2(acc[kk][0], cp, z.u[0]);
                fma2(acc[kk][1], cp, z.u[1]);
            }
        }
    }

#pragma unroll
    for (int kk = 0; kk < 4; kk++) {
        int k = kq * 4 + kk;
        F4U v; v.u[0] = acc[kk][0]; v.u[1] = acc[kk][1];
        st_tf32x4(&d_D2[((size_t)b * 32 + k) * NI + (m0 + ml) * 32 + iq * 4], v.f);
    }
}

// ---------------------------------------------------------------------------
// K3a: out[b][m][(n,i)] = sum_k Ct[m,k] D1[b,k,(n,i)].
// Grid (ct=32, rs=4, b=8), 128 thr. B frags resident; A via one LDG.128
// per (rf,kf) from d_Afrag; each block does 4 rf.
// ---------------------------------------------------------------------------
__global__ void __launch_bounds__(128) k3a_up(float* __restrict__ out) {
    int t = threadIdx.x, lane = t & 31, w = t >> 5;
    int ct = blockIdx.x, rs = blockIdx.y, b = blockIdx.z;
    int gr = lane >> 2, tg = lane & 3;
    int colbase = ct * 256 + w * 64;

    const float* B = d_D1 + (size_t)b * 32 * NI;
    const uint4* Af = (const uint4*)d_Afrag;

    uint32_t bf[4][8][2];
#pragma unroll
    for (int kf = 0; kf < 4; kf++) {
        int r0 = kf * 8 + tg;
#pragma unroll
        for (int cf = 0; cf < 8; cf++) {
            int col = colbase + cf * 8 + gr;
            bf[kf][cf][0] = __float_as_uint(__ldg(&B[(size_t)r0 * NI + col]));
            bf[kf][cf][1] = __float_as_uint(__ldg(&B[(size_t)(r0 + 4) * NI + col]));
        }
    }

#pragma unroll
    for (int rr = 0; rr < 4; rr++) {
        int rf = rs * 4 + rr;
        int r0 = rf * 16;

        U4F a[4];
#pragma unroll
        for (int kf = 0; kf < 4; kf++)
            a[kf].u4 = __ldg(&Af[(rf * 4 + kf) * 32 + lane]);

        float acc[8][4];
#pragma unroll
        for (int cf = 0; cf < 8; cf++)
#pragma unroll
            for (int q = 0; q < 4; q++) acc[cf][q] = 0.f;

#pragma unroll
        for (int cf = 0; cf < 8; cf++)
#pragma unroll
            for (int kf = 0; kf < 4; kf++)
                mma_tf32(acc[cf], a[kf].u, bf[kf][cf][0], bf[kf][cf][1]);

        int r = r0 + gr;
#pragma unroll
        for (int cf = 0; cf < 8; cf++) {
            size_t base = ((size_t)b * 256 + r) * NI + colbase + cf * 8 + 2 * tg;
            *(float2*)&out[base] = make_float2(acc[cf][0], acc[cf][1]);
            *(float2*)&out[base + (size_t)8 * NI] = make_float2(acc[cf][2], acc[cf][3]);
        }
    }
}

// ---------------------------------------------------------------------------
// K3b: out[b][m][n][i] += sum_k Ct[n,k] D2[b,k,(m,i)].  Same; RMW epilogue.
// ---------------------------------------------------------------------------
__global__ void __launch_bounds__(128) k3b_up(float* __restrict__ out) {
    int t = threadIdx.x, lane = t & 31, w = t >> 5;
    int ct = blockIdx.x, rs = blockIdx.y, b = blockIdx.z;
    int gr = lane >> 2, tg = lane & 3;
    int colbase = ct * 256 + w * 64;

    const float* B = d_D2 + (size_t)b * 32 * NI;
    const uint4* Af = (const uint4*)d_Afrag;

    uint32_t bf[4][8][2];
#pragma unroll
    for (int kf = 0; kf < 4; kf++) {
        int r0 = kf * 8 + tg;
#pragma unroll
        for (int cf = 0; cf < 8; cf++) {
            int col = colbase + cf * 8 + gr;
            bf[kf][cf][0] = __float_as_uint(__ldg(&B[(size_t)r0 * NI + col]));
            bf[kf][cf][1] = __float_as_uint(__ldg(&B[(size_t)(r0 + 4) * NI + col]));
        }
    }

#pragma unroll
    for (int rr = 0; rr < 4; rr++) {
        int rf = rs * 4 + rr;
        int r0 = rf * 16;

        U4F a[4];
#pragma unroll
        for (int kf = 0; kf < 4; kf++)
            a[kf].u4 = __ldg(&Af[(rf * 4 + kf) * 32 + lane]);

        float acc[8][4];
#pragma unroll
        for (int cf = 0; cf < 8; cf++)
#pragma unroll
            for (int q = 0; q < 4; q++) acc[cf][q] = 0.f;

#pragma unroll
        for (int cf = 0; cf < 8; cf++)
#pragma unroll
            for (int kf = 0; kf < 4; kf++)
                mma_tf32(acc[cf], a[kf].u, bf[kf][cf][0], bf[kf][cf][1]);

        // rows = n, cols = (m,i): out[b][m][n][i]
#pragma unroll
        for (int cf = 0; cf < 8; cf++) {
            int cb = colbase + cf * 8;        // 8-aligned, one m per cf
            int m  = cb >> 5;
            int ib = (cb & 31) + 2 * tg;
            int n  = r0 + gr;
            size_t ad = ((size_t)b * 256 + m) * NI + n * 32 + ib;
            float2 o0 = *(float2*)&out[ad];
            o0.x += acc[cf][0];
            o0.y += acc[cf][1];
            *(float2*)&out[ad] = o0;
            size_t ad2 = ad + 8 * 32;         // row n+8
            float2 o1 = *(float2*)&out[ad2];
            o1.x += acc[cf][2];
            o1.y += acc[cf][3];
            *(float2*)&out[ad2] = o1;
        }
    }
}

// ---------------------------------------------------------------------------
extern "C" void kernel_launch(void* const* d_in, const int* in_sizes, int n_in,
                              void* d_out, int out_size) {
    const float* x = (const float*)d_in[0];
    float* out = (float*)d_out;

    init_C_kernel<<<32, 256>>>();
    init_A_kernel<<<8, 256>>>();
    k1_down_m<<<dim3(64, 8), 256>>>(x);
    k2_down_n<<<dim3(64, 8), 256>>>(x);
    k3a_up<<<dim3(32, 4, 8), 128>>>(out);
    k3b_up<<<dim3(32, 4, 8), 128>>>(out);
}

// round 17
// speedup vs baseline: 1.0351x; 1.0351x over previous
#include <cuda_runtime.h>
#include <cstdint>

// Filtering_72773925863700
// out[b,m,n,i] = (F x)_along_m + (F x)_along_n,  F = C C^T (256x32 low-rank).
// B=8, M=N=256, I=32, fp32.
//
// Round 17: R16 falsified the occupancy theory (issue pinned ~44% at 2x occ).
// k1/k2 re-fattened for issue mix: 32 fma2 per 12 overhead issues (73% fma
// fraction): k1 = 8k x 8j (R14 shape), k2 = NEW 8k x 8i. k3a/k3b + inits
// unchanged from the 114.7us R15 kernel.

#define BATCH 8
#define MDIM 256
#define NDIM 256
#define IDIM 32
#define KM 32
#define NI (NDIM * IDIM)   // 8192

__device__ float d_C[MDIM * KM];           // C[n][k] fp32 (k1/k2 staging)
__device__ float d_Ct[MDIM * KM];          // C[n][k] tf32-rounded
__device__ float d_Afrag[16 * 4 * 32 * 4]; // [rf][kf][lane][4] mma A frags
__device__ float d_D1[BATCH * KM * NI];    // [b][k][(n,i)]  tf32 values
__device__ float d_D2[BATCH * KM * NI];    // [b][k][(m,i)]  tf32 values

union F4U { float4 f4; uint64_t u[2]; float f[4]; };
union U4F { uint4 u4; uint32_t u[4]; };

__device__ __forceinline__ uint64_t pack2(float c) {
    uint64_t r;
    asm("mov.b64 %0, {%1, %1};" : "=l"(r) : "f"(c));
    return r;
}
__device__ __forceinline__ void fma2(uint64_t& acc, uint64_t a, uint64_t b) {
    asm("fma.rn.f32x2 %0, %1, %2, %0;" : "+l"(acc) : "l"(a), "l"(b));
}
__device__ __forceinline__ uint32_t tf32_bits(float x) {
    uint32_t r;
    asm("cvt.rna.tf32.f32 %0, %1;" : "=r"(r) : "f"(x));
    return r;
}
__device__ __forceinline__ uint32_t sm_addr(const void* p) {
    uint32_t a;
    asm("{ .reg .u64 t; cvta.to.shared.u64 t, %1; cvt.u32.u64 %0, t; }"
        : "=r"(a) : "l"(p));
    return a;
}
__device__ __forceinline__ void mbar_init(uint32_t mbar, uint32_t count) {
    asm volatile("mbarrier.init.shared.b64 [%0], %1;" :: "r"(mbar), "r"(count) : "memory");
}
__device__ __forceinline__ void mbar_expect(uint32_t mbar, uint32_t bytes) {
    asm volatile("mbarrier.arrive.expect_tx.shared.b64 _, [%0], %1;"
                 :: "r"(mbar), "r"(bytes) : "memory");
}
__device__ __forceinline__ void bulk_g2s(uint32_t dst, const void* src,
                                         uint32_t bytes, uint32_t mbar) {
    asm volatile(
        "cp.async.bulk.shared::cta.global.mbarrier::complete_tx::bytes [%0], [%1], %2, [%3];"
        :: "r"(dst), "l"(src), "r"(bytes), "r"(mbar) : "memory");
}
__device__ __forceinline__ void mbar_wait(uint32_t mbar, uint32_t parity) {
    asm volatile(
        "{\n\t"
        ".reg .pred P1;\n\t"
        "WAIT_LOOP_%=:\n\t"
        "mbarrier.try_wait.parity.acquire.cta.shared::cta.b64 P1, [%0], %1;\n\t"
        "@P1 bra.uni WAIT_DONE_%=;\n\t"
        "bra.uni WAIT_LOOP_%=;\n\t"
        "WAIT_DONE_%=:\n\t"
        "}"
        :: "r"(mbar), "r"(parity) : "memory");
}
// mma.sync m16n8k8 tf32: D += A x B (mapping verified R11/R13/R14/R15).
__device__ __forceinline__ void mma_tf32(float* d, const uint32_t* a,
                                         uint32_t b0, uint32_t b1) {
    asm volatile(
        "mma.sync.aligned.m16n8k8.row.col.f32.tf32.tf32.f32 "
        "{%0,%1,%2,%3}, {%4,%5,%6,%7}, {%8,%9}, {%0,%1,%2,%3};"
        : "+f"(d[0]), "+f"(d[1]), "+f"(d[2]), "+f"(d[3])
        : "r"(a[0]), "r"(a[1]), "r"(a[2]), "r"(a[3]), "r"(b0), "r"(b1));
}
__device__ __forceinline__ void st_tf32x4(float* p, const float* v) {
    F4U o;
    o.f[0] = __uint_as_float(tf32_bits(v[0]));
    o.f[1] = __uint_as_float(tf32_bits(v[1]));
    o.f[2] = __uint_as_float(tf32_bits(v[2]));
    o.f[3] = __uint_as_float(tf32_bits(v[3]));
    *(float4*)p = o.f4;
}

// ---------------------------------------------------------------------------
// Init C (fp32 + tf32).
// ---------------------------------------------------------------------------
__global__ void init_C_kernel() {
    int idx = blockIdx.x * 256 + threadIdx.x;   // 8192
    int n = idx >> 5;
    int j = idx & 31;
    const double PI = 3.14159265358979323846;
    const double AMP = 1.4142135623730951 / 16.0;
    double v;
    if (j == 0) {
        v = 1.0 / 16.0;
    } else if (j <= 15) {
        int ph = (j * n) & 255;
        v = AMP * cos(2.0 * PI * (double)ph / 256.0);
    } else if (j <= 30) {
        int k = j - 15;
        int ph = (k * n) & 255;
        v = AMP * sin(2.0 * PI * (double)ph / 256.0);
    } else {
        v = 0.0;
    }
    float f = (float)v;
    d_C[idx]  = f;
    d_Ct[idx] = __uint_as_float(tf32_bits(f));
}

// Pack Ct into mma A-fragment order: [rf][kf][lane] -> float4 (a0,a1,a2,a3).
__global__ void init_A_kernel() {
    int idx = blockIdx.x * 256 + threadIdx.x;   // 2048 = 16*4*32
    int lane = idx & 31;
    int kf = (idx >> 5) & 3;
    int rf = idx >> 7;
    int gr = lane >> 2, tg = lane & 3;
    int r0 = rf * 16, c = kf * 8 + tg;
    float4 v;
    v.x = d_Ct[(r0 + gr) * 32 + c];
    v.y = d_Ct[(r0 + 8 + gr) * 32 + c];
    v.z = d_Ct[(r0 + gr) * 32 + c + 4];
    v.w = d_Ct[(r0 + 8 + gr) * 32 + c + 4];
    ((float4*)d_Afrag)[idx] = v;
}

// ---------------------------------------------------------------------------
// K1: D1[b,k,(n,i)] = sum_m C[m,k] x[b,m,(n,i)].  Scalar fp32, bulk-async.
// Grid (32, 8), 128 thr. Tile [32k x 256j]; 32 chunks of 8 m.
// Thread: ko=t>>5 (8 k), jq=t&31 (j quads at jq*4 and 128+jq*4).
// Per mm: 32 fma2 / (2 x-LDS + 2 c-LDS + 8 pack) -> 73% fma issue fraction.
// ---------------------------------------------------------------------------
__global__ void __launch_bounds__(128) k1_down_m(const float* __restrict__ x) {
    __shared__ __align__(128) float xs[2][8 * 256];
    __shared__ __align__(128) float cs[2][8 * 32];
    __shared__ __align__(8) uint64_t mbar[2];

    int t  = threadIdx.x;
    int b  = blockIdx.y;
    int j0 = blockIdx.x * 256;
    int jq = t & 31;
    int ko = t >> 5;

    const float* xb = x + (size_t)b * (MDIM * NI);
    uint32_t mb0 = sm_addr(&mbar[0]);
    uint32_t mb1 = sm_addr(&mbar[1]);

    if (t == 0) { mbar_init(mb0, 1); mbar_init(mb1, 1); }
    __syncthreads();

    const uint32_t CHUNK_BYTES = 8 * 256 * 4 + 8 * 32 * 4;

    auto issue = [&](int mc, int s) {
        uint32_t mb = s ? mb1 : mb0;
        mbar_expect(mb, CHUNK_BYTES);
#pragma unroll
        for (int mm = 0; mm < 8; mm++)
            bulk_g2s(sm_addr(&xs[s][mm * 256]),
                     &xb[(size_t)(mc * 8 + mm) * NI + j0], 1024, mb);
        bulk_g2s(sm_addr(&cs[s][0]), &d_C[mc * 8 * 32], 1024, mb);
    };

    uint64_t acc[8][4];
#pragma unroll
    for (int a = 0; a < 8; a++)
#pragma unroll
        for (int q = 0; q < 4; q++) acc[a][q] = 0ull;

    if (t == 0) issue(0, 0);
    for (int mc = 0; mc < 32; mc++) {
        int s = mc & 1;
        if (mc + 1 < 32) {
            __syncthreads();
            if (t == 0) issue(mc + 1, s ^ 1);
        }
        mbar_wait(s ? mb1 : mb0, (mc >> 1) & 1);

        const float* xsb = xs[s];
        const float* csb = cs[s];
#pragma unroll
        for (int mm = 0; mm < 8; mm++) {
            F4U x0; x0.f4 = *(const float4*)&xsb[mm * 256 + jq * 4];
            F4U x1; x1.f4 = *(const float4*)&xsb[mm * 256 + 128 + jq * 4];
            F4U c0; c0.f4 = *(const float4*)&csb[mm * 32 + ko * 8];
            F4U c1; c1.f4 = *(const float4*)&csb[mm * 32 + ko * 8 + 4];
            float cv[8] = {c0.f[0], c0.f[1], c0.f[2], c0.f[3],
                           c1.f[0], c1.f[1], c1.f[2], c1.f[3]};
#pragma unroll
            for (int a = 0; a < 8; a++) {
                uint64_t cp = pack2(cv[a]);
                fma2(acc[a][0], cp, x0.u[0]);
                fma2(acc[a][1], cp, x0.u[1]);
                fma2(acc[a][2], cp, x1.u[0]);
                fma2(acc[a][3], cp, x1.u[1]);
            }
        }
    }

#pragma unroll
    for (int a = 0; a < 8; a++) {
        int k = ko * 8 + a;
        F4U v0; v0.u[0] = acc[a][0]; v0.u[1] = acc[a][1];
        F4U v1; v1.u[0] = acc[a][2]; v1.u[1] = acc[a][3];
        st_tf32x4(&d_D1[((size_t)b * 32 + k) * NI + j0 + jq * 4], v0.f);
        st_tf32x4(&d_D1[((size_t)b * 32 + k) * NI + j0 + 128 + jq * 4], v1.f);
    }
}

// ---------------------------------------------------------------------------
// K2: D2[b,k,(m,i)] = sum_n C[n,k] x[b,m,n,i].  Scalar fp32, bulk-async.
// Grid (32, 8), 128 thr. Tile 8 m; 16 chunks of 16 n.
// Thread: kq=t&3 (8 k: kq*8..+7), iq=(t>>2)&3 (8 i: iq*8..+7), ml=t>>4 (8 m).
// Per nn: 32 fma2 / (2 z-LDS + 2 c-LDS + 8 pack) -> 73% fma issue fraction.
// ---------------------------------------------------------------------------
__global__ void __launch_bounds__(128) k2_down_n(const float* __restrict__ x) {
    __shared__ __align__(128) float zs[2][8 * 16 * 32];   // 16 KB each
    __shared__ __align__(128) float ch[2][16 * 32];       //  2 KB each
    __shared__ __align__(8) uint64_t mbar[2];

    int t  = threadIdx.x;
    int b  = blockIdx.y;
    int m0 = blockIdx.x * 8;
    int kq = t & 3;          // 8 k's each
    int iq = (t >> 2) & 3;   // 8 i's each (iq*8 .. +7)
    int ml = t >> 4;         // 0..7

    const float* xb = x + (size_t)b * (MDIM * NI) + (size_t)m0 * NI;
    uint32_t mb0 = sm_addr(&mbar[0]);
    uint32_t mb1 = sm_addr(&mbar[1]);

    if (t == 0) { mbar_init(mb0, 1); mbar_init(mb1, 1); }
    __syncthreads();

    const uint32_t CHUNK_BYTES = 8 * 16 * 32 * 4 + 16 * 32 * 4;   // 18432

    auto issue = [&](int nc, int s) {
        uint32_t mb = s ? mb1 : mb0;
        mbar_expect(mb, CHUNK_BYTES);
#pragma unroll
        for (int m2 = 0; m2 < 8; m2++)
            bulk_g2s(sm_addr(&zs[s][m2 * 16 * 32]),
                     &xb[(size_t)m2 * NI + nc * 16 * 32], 2048, mb);
        bulk_g2s(sm_addr(&ch[s][0]), &d_C[nc * 16 * 32], 2048, mb);
    };

    uint64_t acc[8][4];
#pragma unroll
    for (int kk = 0; kk < 8; kk++)
#pragma unroll
        for (int q = 0; q < 4; q++) acc[kk][q] = 0ull;

    if (t == 0) issue(0, 0);
    for (int nc = 0; nc < 16; nc++) {
        int s = nc & 1;
        if (nc + 1 < 16) {
            __syncthreads();
            if (t == 0) issue(nc + 1, s ^ 1);
        }
        mbar_wait(s ? mb1 : mb0, (nc >> 1) & 1);

        const float* zb = zs[s];
        const float* cb = ch[s];
#pragma unroll
        for (int nn = 0; nn < 16; nn++) {
            F4U z0; z0.f4 = *(const float4*)&zb[(ml * 16 + nn) * 32 + iq * 8];
            F4U z1; z1.f4 = *(const float4*)&zb[(ml * 16 + nn) * 32 + iq * 8 + 4];
            F4U c0; c0.f4 = *(const float4*)&cb[nn * 32 + kq * 8];
            F4U c1; c1.f4 = *(const float4*)&cb[nn * 32 + kq * 8 + 4];
            float cv[8] = {c0.f[0], c0.f[1], c0.f[2], c0.f[3],
                           c1.f[0], c1.f[1], c1.f[2], c1.f[3]};
#pragma unroll
            for (int kk = 0; kk < 8; kk++) {
                uint64_t cp = pack2(cv[kk]);
                fma2(acc[kk][0], cp, z0.u[0]);
                fma2(acc[kk][1], cp, z0.u[1]);
                fma2(acc[kk][2], cp, z1.u[0]);
                fma2(acc[kk][3], cp, z1.u[1]);
            }
        }
    }

#pragma unroll
    for (int kk = 0; kk < 8; kk++) {
        int k = kq * 8 + kk;
        F4U v0; v0.u[0] = acc[kk][0]; v0.u[1] = acc[kk][1];
        F4U v1; v1.u[0] = acc[kk][2]; v1.u[1] = acc[kk][3];
        size_t base = ((size_t)b * 32 + k) * NI + (m0 + ml) * 32 + iq * 8;
        st_tf32x4(&d_D2[base], v0.f);
        st_tf32x4(&d_D2[base + 4], v1.f);
    }
}

// ---------------------------------------------------------------------------
// K3a: out[b][m][(n,i)] = sum_k Ct[m,k] D1[b,k,(n,i)].
// Grid (ct=32, rs=4, b=8), 128 thr. B frags resident; A via one LDG.128
// per (rf,kf) from d_Afrag; each block does 4 rf.
// ---------------------------------------------------------------------------
__global__ void __launch_bounds__(128) k3a_up(float* __restrict__ out) {
    int t = threadIdx.x, lane = t & 31, w = t >> 5;
    int ct = blockIdx.x, rs = blockIdx.y, b = blockIdx.z;
    int gr = lane >> 2, tg = lane & 3;
    int colbase = ct * 256 + w * 64;

    const float* B = d_D1 + (size_t)b * 32 * NI;
    const uint4* Af = (const uint4*)d_Afrag;

    uint32_t bf[4][8][2];
#pragma unroll
    for (int kf = 0; kf < 4; kf++) {
        int r0 = kf * 8 + tg;
#pragma unroll
        for (int cf = 0; cf < 8; cf++) {
            int col = colbase + cf * 8 + gr;
            bf[kf][cf][0] = __float_as_uint(__ldg(&B[(size_t)r0 * NI + col]));
            bf[kf][cf][1] = __float_as_uint(__ldg(&B[(size_t)(r0 + 4) * NI + col]));
        }
    }

#pragma unroll
    for (int rr = 0; rr < 4; rr++) {
        int rf = rs * 4 + rr;
        int r0 = rf * 16;

        U4F a[4];
#pragma unroll
        for (int kf = 0; kf < 4; kf++)
            a[kf].u4 = __ldg(&Af[(rf * 4 + kf) * 32 + lane]);

        float acc[8][4];
#pragma unroll
        for (int cf = 0; cf < 8; cf++)
#pragma unroll
            for (int q = 0; q < 4; q++) acc[cf][q] = 0.f;

#pragma unroll
        for (int cf = 0; cf < 8; cf++)
#pragma unroll
            for (int kf = 0; kf < 4; kf++)
                mma_tf32(acc[cf], a[kf].u, bf[kf][cf][0], bf[kf][cf][1]);

        int r = r0 + gr;
#pragma unroll
        for (int cf = 0; cf < 8; cf++) {
            size_t base = ((size_t)b * 256 + r) * NI + colbase + cf * 8 + 2 * tg;
            *(float2*)&out[base] = make_float2(acc[cf][0], acc[cf][1]);
            *(float2*)&out[base + (size_t)8 * NI] = make_float2(acc[cf][2], acc[cf][3]);
        }
    }
}

// ---------------------------------------------------------------------------
// K3b: out[b][m][n][i] += sum_k Ct[n,k] D2[b,k,(m,i)].  Same; RMW epilogue.
// ---------------------------------------------------------------------------
__global__ void __launch_bounds__(128) k3b_up(float* __restrict__ out) {
    int t = threadIdx.x, lane = t & 31, w = t >> 5;
    int ct = blockIdx.x, rs = blockIdx.y, b = blockIdx.z;
    int gr = lane >> 2, tg = lane & 3;
    int colbase = ct * 256 + w * 64;

    const float* B = d_D2 + (size_t)b * 32 * NI;
    const uint4* Af = (const uint4*)d_Afrag;

    uint32_t bf[4][8][2];
#pragma unroll
    for (int kf = 0; kf < 4; kf++) {
        int r0 = kf * 8 + tg;
#pragma unroll
        for (int cf = 0; cf < 8; cf++) {
            int col = colbase + cf * 8 + gr;
            bf[kf][cf][0] = __float_as_uint(__ldg(&B[(size_t)r0 * NI + col]));
            bf[kf][cf][1] = __float_as_uint(__ldg(&B[(size_t)(r0 + 4) * NI + col]));
        }
    }

#pragma unroll
    for (int rr = 0; rr < 4; rr++) {
        int rf = rs * 4 + rr;
        int r0 = rf * 16;

        U4F a[4];
#pragma unroll
        for (int kf = 0; kf < 4; kf++)
            a[kf].u4 = __ldg(&Af[(rf * 4 + kf) * 32 + lane]);

        float acc[8][4];
#pragma unroll
        for (int cf = 0; cf < 8; cf++)
#pragma unroll
            for (int q = 0; q < 4; q++) acc[cf][q] = 0.f;

#pragma unroll
        for (int cf = 0; cf < 8; cf++)
#pragma unroll
            for (int kf = 0; kf < 4; kf++)
                mma_tf32(acc[cf], a[kf].u, bf[kf][cf][0], bf[kf][cf][1]);

        // rows = n, cols = (m,i): out[b][m][n][i]
#pragma unroll
        for (int cf = 0; cf < 8; cf++) {
            int cb = colbase + cf * 8;        // 8-aligned, one m per cf
            int m  = cb >> 5;
            int ib = (cb & 31) + 2 * tg;
            int n  = r0 + gr;
            size_t ad = ((size_t)b * 256 + m) * NI + n * 32 + ib;
            float2 o0 = *(float2*)&out[ad];
            o0.x += acc[cf][0];
            o0.y += acc[cf][1];
            *(float2*)&out[ad] = o0;
            size_t ad2 = ad + 8 * 32;         // row n+8
            float2 o1 = *(float2*)&out[ad2];
            o1.x += acc[cf][2];
            o1.y += acc[cf][3];
            *(float2*)&out[ad2] = o1;
        }
    }
}

// ---------------------------------------------------------------------------
extern "C" void kernel_launch(void* const* d_in, const int* in_sizes, int n_in,
                              void* d_out, int out_size) {
    const float* x = (const float*)d_in[0];
    float* out = (float*)d_out;

    init_C_kernel<<<32, 256>>>();
    init_A_kernel<<<8, 256>>>();
    k1_down_m<<<dim3(32, 8), 128>>>(x);
    k2_down_n<<<dim3(32, 8), 128>>>(x);
    k3a_up<<<dim3(32, 4, 8), 128>>>(out);
    k3b_up<<<dim3(32, 4, 8), 128>>>(out);
}